// round 11
// baseline (speedup 1.0000x reference)
#include <cuda_runtime.h>

// Problem constants
#define B_    2048
#define T_    512
#define FIN_  32
#define H_    64
#define G4_   256        // 4*H
#define HOR_  48
#define FOUT_ 8
#define NROW  14         // batch rows per CTA
#define NCTA  147        // ceil(2048/14)
#define RTHREADS 1024
#define G0ROW (B_ * G4_)

typedef unsigned long long u64;

// ---------------- scratch (__device__ globals; no cudaMalloc allowed) ----------------
// d_g0 layout: [t][b][unit*4 + gate]  (float4 per hidden unit = {i,f,g,o})
__device__ float d_g0[(size_t)T_ * B_ * G4_];
__device__ float d_WcT[FIN_ * G4_];             // combined (Wih0 @ W_emb), packed-channel order
__device__ float d_bc[G4_];                     // combined layer0 bias, packed-channel order
__device__ float d_wih0P[H_ * G4_];             // decoder Wih[0], woff-packed

// ---------------- fast activations ----------------
__device__ __forceinline__ float sigf(float x) {
    return __fdividef(1.0f, 1.0f + __expf(-x));
}
__device__ __forceinline__ float tanh_f(float x) {
    return __fdividef(2.0f, 1.0f + __expf(-2.0f * x)) - 1.0f;
}

// ---------------- packed fp32x2 helpers ----------------
__device__ __forceinline__ u64 fma2(u64 a, u64 b, u64 c) {
    u64 d;
    asm("fma.rn.f32x2 %0, %1, %2, %3;" : "=l"(d) : "l"(a), "l"(b), "l"(c));
    return d;
}
__device__ __forceinline__ float hadd2(u64 a) {
    float lo, hi;
    asm("mov.b64 {%0, %1}, %2;" : "=f"(lo), "=f"(hi) : "l"(a));
    return lo + hi;
}

// per-row-half named barrier: rh 0 -> id 1 (warps 0-15), rh 1 -> id 2 (warps 16-31)
__device__ __forceinline__ void barh(int rh) {
    asm volatile("bar.sync %0, 512;" :: "r"(rh + 1) : "memory");
}

// packed output-channel index: original gate g (0..255) -> unit*4 + gate_slot
__device__ __forceinline__ int pidx(int g) { return ((g & 63) << 2) + (g >> 6); }
// weight packing for W[g][k] within one 256x64 matrix (16384 floats):
// [ks(4)][kq(4)][pair(2)][gp(128)][{g0k_even,g0k_odd,g1k_even,g1k_odd}]
__device__ __forceinline__ int woff(int g, int k) {
    int c = pidx(g);
    return ((k >> 4) << 12) + (((k >> 2) & 3) << 10) + (((k >> 1) & 1) << 9)
         + ((c >> 1) << 2) + ((c & 1) << 1) + (k & 1);
}

// ---------------- prep: combined weights / packed transposes ----------------
__global__ void prep_kernel(const float* __restrict__ W_emb, const float* __restrict__ b_emb,
                            const float* __restrict__ encWih, const float* __restrict__ encbih,
                            const float* __restrict__ encbhh, const float* __restrict__ decWih)
{
    int g  = threadIdx.x;   // original gate index 0..255
    int bb = blockIdx.x;    // 0..32
    float wrow[H_];
#pragma unroll
    for (int h = 0; h < H_; h++) wrow[h] = encWih[g * H_ + h];

    if (bb == FIN_) {
        float b = encbih[g] + encbhh[g];
#pragma unroll
        for (int h = 0; h < H_; h++) b = fmaf(wrow[h], b_emb[h], b);
        d_bc[pidx(g)] = b;
#pragma unroll
        for (int k = 0; k < H_; k++)
            d_wih0P[woff(g, k)] = decWih[g * H_ + k];
    } else {
        int f = bb;
        float s = 0.f;
#pragma unroll
        for (int h = 0; h < H_; h++) s = fmaf(wrow[h], W_emb[h * FIN_ + f], s);
        d_WcT[f * G4_ + pidx(g)] = s;
    }
}

// ---------------- GEMM: d_g0[t][b][c] = X[b][t][:] @ WcT[:, c] + bc[c] ----------------
__global__ void __launch_bounds__(256)
emb_gemm(const float* __restrict__ X)
{
    __shared__ float sX[128 * FIN_];
    const int t   = blockIdx.y;
    const int b0  = blockIdx.x * 128;
    const int tid = threadIdx.x;   // packed channel

#pragma unroll
    for (int q = 0; q < 4; q++) {
        int lin = tid + q * 256;
        int rr = lin >> 3, f4 = lin & 7;
        float4 v = *(const float4*)(X + ((size_t)(b0 + rr) * T_ + t) * FIN_ + f4 * 4);
        *(float4*)(sX + rr * FIN_ + f4 * 4) = v;
    }
    float w[FIN_];
#pragma unroll
    for (int f = 0; f < FIN_; f++) w[f] = d_WcT[f * G4_ + tid];
    const float bias = d_bc[tid];
    __syncthreads();

    float* dst = d_g0 + (size_t)t * B_ * G4_ + (size_t)b0 * G4_ + tid;
#pragma unroll 2
    for (int rr = 0; rr < 128; rr++) {
        float a = bias;
        const float* xr = sX + rr * FIN_;
#pragma unroll
        for (int f = 0; f < FIN_; f += 4) {
            float4 x = *(const float4*)(xr + f);
            a = fmaf(x.x, w[f + 0], a);
            a = fmaf(x.y, w[f + 1], a);
            a = fmaf(x.z, w[f + 2], a);
            a = fmaf(x.w, w[f + 3], a);
        }
        dst[(size_t)rr * G4_] = a;
    }
}

// ---------------- matvec: 7 rows x 16 k x 2 channels (2gp, 2gp+1) ----------------
// hb = h row base + ks*16 ; wb = matrix base + ks*4096 (smem, woff layout)
__device__ __forceinline__ void mv2(u64 acc[7][2], const float* __restrict__ hb,
                                    const float* __restrict__ wb, int gp)
{
#pragma unroll
    for (int kq = 0; kq < 4; kq++) {
        const float* wp = wb + kq * 1024 + (gp << 2);
        ulonglong2 wA = *(const ulonglong2*)(wp);         // k pair (0,1) x {c0,c1}
        ulonglong2 wB = *(const ulonglong2*)(wp + 512);   // k pair (2,3) x {c0,c1}
        const float* hq = hb + kq * 4;
#pragma unroll
        for (int r = 0; r < 7; r++) {
            ulonglong2 h = *(const ulonglong2*)(hq + r * 64);
            acc[r][0] = fma2(h.x, wA.x, acc[r][0]);
            acc[r][1] = fma2(h.x, wA.y, acc[r][1]);
            acc[r][0] = fma2(h.y, wB.x, acc[r][0]);
            acc[r][1] = fma2(h.y, wB.y, acc[r][1]);
        }
    }
}

// same, weights streamed from global (decoder dWih0, L2-resident)
__device__ __forceinline__ void mv2g(u64 acc[7][2], const float* __restrict__ hb,
                                     const float* __restrict__ wb, int gp)
{
#pragma unroll
    for (int kq = 0; kq < 4; kq++) {
        const float* wp = wb + kq * 1024 + (gp << 2);
        ulonglong2 wA = __ldg((const ulonglong2*)(wp));
        ulonglong2 wB = __ldg((const ulonglong2*)(wp + 512));
        const float* hq = hb + kq * 4;
#pragma unroll
        for (int r = 0; r < 7; r++) {
            ulonglong2 h = *(const ulonglong2*)(hq + r * 64);
            acc[r][0] = fma2(h.x, wA.x, acc[r][0]);
            acc[r][1] = fma2(h.x, wA.y, acc[r][1]);
            acc[r][0] = fma2(h.y, wB.x, acc[r][0]);
            acc[r][1] = fma2(h.y, wB.y, acc[r][1]);
        }
    }
}

__device__ __forceinline__ void store_p(const u64 a[7][2], float* __restrict__ buf,
                                        int rbase, int gp)
{
#pragma unroll
    for (int r = 0; r < 7; r++) {
        float2 v; v.x = hadd2(a[r][0]); v.y = hadd2(a[r][1]);
        *(float2*)(buf + (rbase + r) * G4_ + (gp << 1)) = v;
    }
}

__device__ __forceinline__ void add_p(const u64 a[7][2], float* __restrict__ buf,
                                      int rbase, int gp)
{
#pragma unroll
    for (int r = 0; r < 7; r++) {
        float* p = buf + (rbase + r) * G4_ + (gp << 1);
        float2 v = *(const float2*)(p);
        v.x += hadd2(a[r][0]); v.y += hadd2(a[r][1]);
        *(float2*)(p) = v;
    }
}

// pointwise LSTM for one element; gates float4 {i,f,g,o}; c in register
__device__ __forceinline__ void lstm_e(float4 g4, float& c, float* __restrict__ hout)
{
    float cn = sigf(g4.y) * c + sigf(g4.x) * tanh_f(g4.z);
    c = cn;
    *hout = sigf(g4.w) * tanh_f(cn);
}

__device__ __forceinline__ float4 sum3(float4 a, float4 b, float4 d)
{
    float4 v;
    v.x = a.x + b.x + d.x; v.y = a.y + b.y + d.y;
    v.z = a.z + b.z + d.z; v.w = a.w + b.w + d.w;
    return v;
}

// smem: sW 3*16384 | sH 2*896 | sP0 3584 | sP1 3584  = 58112 floats = 232448 B
#define SMEM_FLOATS (3*16384 + 2*896 + 3584 + 3584)
#define SMEM_BYTES  (SMEM_FLOATS * 4)

__global__ void __launch_bounds__(RTHREADS, 1)
rnn_kernel(const float* __restrict__ encWih, const float* __restrict__ encWhh,
           const float* __restrict__ encbih, const float* __restrict__ encbhh,
           const float* __restrict__ decWih, const float* __restrict__ decWhh,
           const float* __restrict__ decbih, const float* __restrict__ decbhh,
           const float* __restrict__ Wreg,   const float* __restrict__ breg,
           float* __restrict__ out)
{
    extern __shared__ float sm[];
    float* sW  = sm;                 // 3 matrices, woff-packed
    float* sH  = sW + 49152;         // [layer][14][64]
    float* sP0 = sH + 1792;          // partial gate buffer A [14][256]
    float* sP1 = sP0 + 3584;         // partial gate buffer B [14][256]

    const int tid   = threadIdx.x;
    const int gp    = tid & 127;            // channel pair (channels 2gp, 2gp+1)
    const int ks    = (tid >> 7) & 3;       // k-split (k in [16ks, 16ks+16))
    const int rh    = tid >> 9;             // row-half
    const int rbase = rh * 7;
    const int lt    = tid & 511;            // lane within row-half
    const int b0    = blockIdx.x * NROW;

    float* myBuf = (ks < 2) ? sP0 : sP1;
    const bool addL0 = ((ks & 1) == 0);     // L0: even ks adds; odd stores. L1: swapped.

    // pack encoder weights: slot0=encWhh[0], slot1=encWih[1], slot2=encWhh[1]
    for (int i = tid; i < 16384; i += RTHREADS) {
        int g = i >> 6, k = i & 63;
        int dst = woff(g, k);
        sW[dst]         = encWhh[i];
        sW[16384 + dst] = encWih[16384 + i];
        sW[32768 + dst] = encWhh[16384 + i];
    }
    for (int i = tid; i < 2 * 896; i += RTHREADS) sH[i] = 0.f;
    __syncthreads();

    // update-phase element (per rh: 448 elems over 512 threads; lt<448 active)
    const bool upd_act = (lt < 7 * H_);
    const int r0 = lt >> 6, j0 = lt & 63;
    const int eoff0 = (rbase + r0) * G4_ + (j0 << 2);
    float* h0p0 = sH + (rbase + r0) * 64 + j0;
    float* h1p0 = h0p0 + 896;

    // encoder L1 bias per element (registers)
    float4 b1a = make_float4(0.f, 0.f, 0.f, 0.f);
    if (upd_act) {
        b1a.x = encbih[256 + j0]       + encbhh[256 + j0];
        b1a.y = encbih[256 + 64 + j0]  + encbhh[256 + 64 + j0];
        b1a.z = encbih[256 + 128 + j0] + encbhh[256 + 128 + j0];
        b1a.w = encbih[256 + 192 + j0] + encbhh[256 + 192 + j0];
    }

    // x-part gmem offset for update element (clamped for tail CTA)
    int bcl0 = b0 + rbase + r0; if (bcl0 >= B_) bcl0 = B_ - 1;
    const size_t gxo0 = (size_t)bcl0 * G4_ + (j0 << 2);
    float4 gx0 = upd_act ? *(const float4*)(d_g0 + gxo0) : make_float4(0.f, 0.f, 0.f, 0.f);

    const float* hb0 = sH + rbase * 64 + ks * 16;
    const float* hb1 = hb0 + 896;
    float c0 = 0.f, c1 = 0.f;

    // -------------------- encoder: 512 steps --------------------
    for (int t = 0; t < T_; t++) {
        u64 acc[7][2];
        // ---- layer 0: Whh0 x h0 ----
#pragma unroll
        for (int r = 0; r < 7; r++) { acc[r][0] = 0ull; acc[r][1] = 0ull; }
        mv2(acc, hb0, sW + ks * 4096, gp);
        if (!addL0) store_p(acc, myBuf, rbase, gp);
        barh(rh);
        if (addL0) add_p(acc, myBuf, rbase, gp);
        barh(rh);
        // update L0: gates = sP0 + sP1 + x-part
        if (upd_act) {
            float4 p = *(const float4*)(sP0 + eoff0);
            float4 q = *(const float4*)(sP1 + eoff0);
            lstm_e(sum3(p, q, gx0), c0, h0p0);
            if (t + 1 < T_) {   // prefetch next step's x-part
                gx0 = *(const float4*)(d_g0 + (size_t)(t + 1) * G0ROW + gxo0);
            }
        }
        barh(rh);
        // ---- layer 1: Wih1 x h0_new + Whh1 x h1 ----
#pragma unroll
        for (int r = 0; r < 7; r++) { acc[r][0] = 0ull; acc[r][1] = 0ull; }
        mv2(acc, hb0, sW + 16384 + ks * 4096, gp);
        mv2(acc, hb1, sW + 32768 + ks * 4096, gp);
        if (addL0) store_p(acc, myBuf, rbase, gp);      // roles swapped
        barh(rh);
        if (!addL0) add_p(acc, myBuf, rbase, gp);
        barh(rh);
        // update L1: gates = sP0 + sP1 + bias
        if (upd_act) {
            float4 p = *(const float4*)(sP0 + eoff0);
            float4 q = *(const float4*)(sP1 + eoff0);
            lstm_e(sum3(p, q, b1a), c1, h1p0);
        }
        barh(rh);
    }

    // -------------------- decoder setup (sW shared across rh: full syncs) --------------------
    __syncthreads();
    for (int i = tid; i < 16384; i += RTHREADS) {
        int g = i >> 6, k = i & 63;
        int dst = woff(g, k);
        sW[dst]         = decWhh[i];             // dWhh0
        sW[16384 + dst] = decWih[16384 + i];     // dWih1
        sW[32768 + dst] = decWhh[16384 + i];     // dWhh1
    }
    float4 db0a = make_float4(0.f, 0.f, 0.f, 0.f);
    float4 db1a = make_float4(0.f, 0.f, 0.f, 0.f);
    if (upd_act) {
        db0a.x = decbih[j0]       + decbhh[j0];
        db0a.y = decbih[64 + j0]  + decbhh[64 + j0];
        db0a.z = decbih[128 + j0] + decbhh[128 + j0];
        db0a.w = decbih[192 + j0] + decbhh[192 + j0];
        db1a.x = decbih[256 + j0]       + decbhh[256 + j0];
        db1a.y = decbih[256 + 64 + j0]  + decbhh[256 + 64 + j0];
        db1a.z = decbih[256 + 128 + j0] + decbhh[256 + 128 + j0];
        db1a.w = decbih[256 + 192 + j0] + decbhh[256 + 192 + j0];
    }
    c0 = c1 = 0.f;                               // c reset; h carries over
    __syncthreads();

    // -------------------- decoder: 48 steps --------------------
    for (int t = 0; t < HOR_; t++) {
        u64 acc[7][2];
        // ---- layer 0: dWih0 x h1_prev (gmem weights) + dWhh0 x h0 ----
#pragma unroll
        for (int r = 0; r < 7; r++) { acc[r][0] = 0ull; acc[r][1] = 0ull; }
        mv2g(acc, hb1, d_wih0P + ks * 4096, gp);
        mv2 (acc, hb0, sW + ks * 4096, gp);
        if (!addL0) store_p(acc, myBuf, rbase, gp);
        barh(rh);
        if (addL0) add_p(acc, myBuf, rbase, gp);
        barh(rh);
        if (upd_act) {
            float4 p = *(const float4*)(sP0 + eoff0);
            float4 q = *(const float4*)(sP1 + eoff0);
            lstm_e(sum3(p, q, db0a), c0, h0p0);
        }
        barh(rh);
        // ---- layer 1 ----
#pragma unroll
        for (int r = 0; r < 7; r++) { acc[r][0] = 0ull; acc[r][1] = 0ull; }
        mv2(acc, hb0, sW + 16384 + ks * 4096, gp);
        mv2(acc, hb1, sW + 32768 + ks * 4096, gp);
        if (addL0) store_p(acc, myBuf, rbase, gp);
        barh(rh);
        if (!addL0) add_p(acc, myBuf, rbase, gp);
        barh(rh);
        if (upd_act) {
            float4 p = *(const float4*)(sP0 + eoff0);
            float4 q = *(const float4*)(sP1 + eoff0);
            lstm_e(sum3(p, q, db1a), c1, h1p0);
        }
        barh(rh);
        // regression head: y = h1_new @ Wreg^T + breg (Wreg via L2)
        if (lt < 7 * FOUT_) {
            int rloc = lt >> 3, o = lt & 7;
            int b = b0 + rbase + rloc;
            if (b < B_) {
                float a = __ldg(&breg[o]);
                const float* hr = sH + 896 + (rbase + rloc) * 64;
#pragma unroll
                for (int k = 0; k < H_; k += 4) {
                    float4 h4 = *(const float4*)(hr + k);
                    float4 w4 = __ldg((const float4*)(Wreg + o * H_ + k));
                    a = fmaf(h4.x, w4.x, a);
                    a = fmaf(h4.y, w4.y, a);
                    a = fmaf(h4.z, w4.z, a);
                    a = fmaf(h4.w, w4.w, a);
                }
                out[((size_t)b * HOR_ + t) * FOUT_ + o] = a;
            }
        }
    }
}

// ---------------- launch ----------------
extern "C" void kernel_launch(void* const* d_in, const int* in_sizes, int n_in,
                              void* d_out, int out_size)
{
    const float* X      = (const float*)d_in[0];
    // d_in[1] = X_mask : all-ones, unused by reference
    const float* W_emb  = (const float*)d_in[2];
    const float* b_emb  = (const float*)d_in[3];
    const float* encWih = (const float*)d_in[4];
    const float* encWhh = (const float*)d_in[5];
    const float* encbih = (const float*)d_in[6];
    const float* encbhh = (const float*)d_in[7];
    const float* decWih = (const float*)d_in[8];
    const float* decWhh = (const float*)d_in[9];
    const float* decbih = (const float*)d_in[10];
    const float* decbhh = (const float*)d_in[11];
    const float* W_reg  = (const float*)d_in[12];
    const float* b_reg  = (const float*)d_in[13];
    float* out = (float*)d_out;

    cudaFuncSetAttribute(rnn_kernel, cudaFuncAttributeMaxDynamicSharedMemorySize, SMEM_BYTES);

    prep_kernel<<<FIN_ + 1, 256>>>(W_emb, b_emb, encWih, encbih, encbhh, decWih);
    emb_gemm<<<dim3(B_ / 128, T_), 256>>>(X);
    rnn_kernel<<<NCTA, RTHREADS, SMEM_BYTES>>>(encWih, encWhh, encbih, encbhh,
                                               decWih, decWhh, decbih, decbhh,
                                               W_reg, b_reg, out);
}